// round 13
// baseline (speedup 1.0000x reference)
#include <cuda_runtime.h>
#include <math.h>

// Problem dims
#define BQ 8
#define TT 2048
#define EE 1024
#define HH 1024

// GEMM tile config: CTA 128x128, 4 warps (2m x 2n), warp tile 64x64,
// K staged in 32-wide chunks, 3-stage cp.async ring.
#define BM 128
#define BN 128
#define BKT 32
#define LDAS 36                        // 32 + 4 pad -> conflict-free LDS
#define STG_WORDS (BM * LDAS)          // 4608 words = 18432 B per operand stage
#define STAGES 3
#define SMEM_GEMM (STAGES * 2 * STG_WORDS * 4)  // 110592 B

// Scratch (allocation-free rule: __device__ globals; device-side access ONLY —
// taking these symbols' addresses from host code was the R7 silent-zero bug)
__device__ float g_x [(long long)BQ * TT * EE];   // tf32-rounded x
__device__ float g_wq[(long long)HH * EE];        // tf32-rounded weights
__device__ float g_wk[(long long)HH * EE];
__device__ float g_wv[(long long)HH * EE];
__device__ float g_q [(long long)BQ * TT * HH];   // rounded at store
__device__ float g_k [(long long)BQ * TT * HH];
__device__ float g_v [(long long)BQ * TT * HH];
__device__ float g_vt[(long long)BQ * HH * TT];   // V transposed [b][h][s]
__device__ float g_s [(long long)BQ * TT * TT];   // scores / probs

__device__ __forceinline__ unsigned f2tf(float x) {
    unsigned r;
    asm("cvt.rna.tf32.f32 %0, %1;" : "=r"(r) : "f"(x));
    return r;
}
__device__ __forceinline__ float roundtf(float x) { return __uint_as_float(f2tf(x)); }

__device__ __forceinline__ void mma_tf32(float* c,
                                         unsigned a0, unsigned a1, unsigned a2, unsigned a3,
                                         unsigned b0, unsigned b1) {
    asm volatile(
        "mma.sync.aligned.m16n8k8.row.col.f32.tf32.tf32.f32 "
        "{%0,%1,%2,%3}, {%4,%5,%6,%7}, {%8,%9}, {%0,%1,%2,%3};"
        : "+f"(c[0]), "+f"(c[1]), "+f"(c[2]), "+f"(c[3])
        : "r"(a0), "r"(a1), "r"(a2), "r"(a3), "r"(b0), "r"(b1));
}

__device__ __forceinline__ unsigned smem_u32(const void* p) {
    return (unsigned)__cvta_generic_to_shared(p);
}
__device__ __forceinline__ void cp_async16(unsigned dst, const void* src) {
    asm volatile("cp.async.cg.shared.global [%0], [%1], 16;" :: "r"(dst), "l"(src));
}
__device__ __forceinline__ void cp_commit() { asm volatile("cp.async.commit_group;"); }
__device__ __forceinline__ void cp_wait1()  { asm volatile("cp.async.wait_group 1;"); }

// ---------------------------------------------------------------------------
// C[M,N] = scale * A[M,K] * B[N,K]^T  (A,B row-major, K contiguous for both).
// Inputs PRE-ROUNDED to tf32. 128 threads, 4 warps (2m x 2n), warp tile
// 64x64, m16n8k8 tf32 mma -> 1.0 LDS per HMMA (vs 1.5 at 32x64).
// 3-stage cp.async ring, wait_group 1, ONE barrier per BKT=32 k-chunk.
// CAUSAL: store only where global col <= global row.
// ROUND:  store outputs rounded to tf32.
// ---------------------------------------------------------------------------
template <bool CAUSAL, bool ROUND>
__device__ __forceinline__ void gemm_nt(const float* __restrict__ A,
                                        const float* __restrict__ B,
                                        float* __restrict__ C,
                                        int lda, int ldb, int ldc,
                                        int K, int m0, int n0, float scale) {
    extern __shared__ unsigned sm[];

    const int tid = threadIdx.x;
    const int warp = tid >> 5, lane = tid & 31;
    const int wm = warp >> 1;  // 0..1 (64 rows each)
    const int wn = warp & 1;   // 0..1 (64 cols each)

    float acc[4][8][4];
#pragma unroll
    for (int i = 0; i < 4; i++)
#pragma unroll
        for (int j = 0; j < 8; j++)
#pragma unroll
            for (int r = 0; r < 4; r++) acc[i][j][r] = 0.f;

    // Staging: 16B chunks. Per stage each operand is 128 rows x 32 words =
    // 1024 chunks; 128 threads x 8 chunks. row = chunk>>3, word = (chunk&7)*4.
    auto issue = [&](int s, int ktw) {
        unsigned* as = sm + s * 2 * STG_WORDS;
        unsigned* bs = as + STG_WORDS;
#pragma unroll
        for (int p = 0; p < 8; p++) {
            int chunk = tid + 128 * p;
            int row = chunk >> 3;
            int cw = (chunk & 7) * 4;
            cp_async16(smem_u32(&as[row * LDAS + cw]),
                       A + (size_t)(m0 + row) * lda + ktw + cw);
            cp_async16(smem_u32(&bs[row * LDAS + cw]),
                       B + (size_t)(n0 + row) * ldb + ktw + cw);
        }
        cp_commit();
    };

    const int nk = K / BKT;   // >= 4 for all call sites
    issue(0, 0);
    issue(1, BKT);

    for (int kt = 0; kt < nk; kt++) {
        cp_wait1();           // stage kt resident (kt+1 may still be in flight)
        __syncthreads();
        // Stage (kt+2)%3 was last read in iteration kt-1, which every warp
        // finished before this barrier; issue strictly after it.
        if (kt + 2 < nk) issue((kt + 2) % STAGES, (kt + 2) * BKT);

        const unsigned* as = sm + (kt % STAGES) * 2 * STG_WORDS;
        const unsigned* bs = as + STG_WORDS;

#pragma unroll
        for (int ks = 0; ks < BKT; ks += 8) {
            unsigned a[4][4], b[8][2];
#pragma unroll
            for (int i = 0; i < 4; i++) {
                int r = wm * 64 + i * 16 + (lane >> 2);
                int c = ks + (lane & 3);
                a[i][0] = as[r * LDAS + c];
                a[i][1] = as[(r + 8) * LDAS + c];
                a[i][2] = as[r * LDAS + c + 4];
                a[i][3] = as[(r + 8) * LDAS + c + 4];
            }
#pragma unroll
            for (int j = 0; j < 8; j++) {
                int n = wn * 64 + j * 8 + (lane >> 2);
                int c = ks + (lane & 3);
                b[j][0] = bs[n * LDAS + c];
                b[j][1] = bs[n * LDAS + c + 4];
            }
#pragma unroll
            for (int i = 0; i < 4; i++)
#pragma unroll
                for (int j = 0; j < 8; j++)
                    mma_tf32(acc[i][j], a[i][0], a[i][1], a[i][2], a[i][3],
                             b[j][0], b[j][1]);
        }
    }

#pragma unroll
    for (int i = 0; i < 4; i++) {
        int rbase = m0 + wm * 64 + i * 16 + (lane >> 2);
#pragma unroll
        for (int j = 0; j < 8; j++) {
            int cn = n0 + wn * 64 + j * 8 + (lane & 3) * 2;
#pragma unroll
            for (int h = 0; h < 2; h++) {
                int r = rbase + h * 8;
                float v0 = acc[i][j][2 * h + 0] * scale;
                float v1 = acc[i][j][2 * h + 1] * scale;
                if (ROUND) { v0 = roundtf(v0); v1 = roundtf(v1); }
                if (CAUSAL) {
                    if (cn <= r)     C[(size_t)r * ldc + cn]     = v0;
                    if (cn + 1 <= r) C[(size_t)r * ldc + cn + 1] = v1;
                } else {
                    *reinterpret_cast<float2*>(C + (size_t)r * ldc + cn) =
                        make_float2(v0, v1);
                }
            }
        }
    }
}

// ---------------------------------------------------------------------------
// Kernels
// ---------------------------------------------------------------------------

// tf32 pre-round; dst selected DEVICE-SIDE.
__global__ void __launch_bounds__(256) round_kernel(const float4* __restrict__ src,
                                                    int which) {
    float4* dst;
    switch (which) {
        case 0:  dst = reinterpret_cast<float4*>(g_x);  break;
        case 1:  dst = reinterpret_cast<float4*>(g_wq); break;
        case 2:  dst = reinterpret_cast<float4*>(g_wk); break;
        default: dst = reinterpret_cast<float4*>(g_wv); break;
    }
    int i = blockIdx.x * 256 + threadIdx.x;
    float4 v = src[i];
    dst[i] = make_float4(roundtf(v.x), roundtf(v.y), roundtf(v.z), roundtf(v.w));
}

// Q/K/V = x @ W^T ; grid (HH/BN, (BQ*TT)/BM, 3), 128 threads
__global__ void __launch_bounds__(128) qkv_kernel() {
    const float* W;
    float* out;
    switch (blockIdx.z) {
        case 0: W = g_wq; out = g_q; break;
        case 1: W = g_wk; out = g_k; break;
        default: W = g_wv; out = g_v; break;
    }
    gemm_nt<false, true>(g_x, W, out, EE, EE, HH, EE,
                         blockIdx.y * BM, blockIdx.x * BN, 1.0f);
}

// Vt[b][h][s] = V[b][s][h] ; grid (HH/32, TT/32, BQ), block (32, 8)
__global__ void __launch_bounds__(256) transpose_kernel() {
    __shared__ float tile[32][33];
    const int b = blockIdx.z;
    const float* src = g_v + (size_t)b * TT * HH;
    float* dst = g_vt + (size_t)b * HH * TT;
    const int h0 = blockIdx.x * 32, s0 = blockIdx.y * 32;
    const int tx = threadIdx.x, ty = threadIdx.y;
#pragma unroll
    for (int i = 0; i < 4; i++)
        tile[ty + 8 * i][tx] = src[(size_t)(s0 + ty + 8 * i) * HH + h0 + tx];
    __syncthreads();
#pragma unroll
    for (int i = 0; i < 4; i++)
        dst[(size_t)(h0 + ty + 8 * i) * TT + s0 + tx] = tile[tx][ty + 8 * i];
}

// S = (Q K^T) * E^-0.5, causal; grid (TT/BN, TT/BM, BQ), 128 threads
__global__ void __launch_bounds__(128) score_kernel() {
    int b = blockIdx.z;
    int m0 = blockIdx.y * BM, n0 = blockIdx.x * BN;
    if (n0 > m0) return;  // tile entirely above the diagonal -> never read
    const float* Q = g_q + (size_t)b * TT * HH;
    const float* Kp = g_k + (size_t)b * TT * HH;
    float* S = g_s + (size_t)b * TT * TT;
    gemm_nt<true, false>(Q, Kp, S, HH, HH, TT, HH, m0, n0, 0.03125f);  // 1024^-0.5
}

// Row-wise causal softmax in place on g_s; stores tf32-rounded P.
// Zero-fills only up to the 128-rounded boundary pv reads. grid (BQ*TT)
__global__ void __launch_bounds__(256) softmax_kernel() {
    const int row = blockIdx.x;
    const int b = row >> 11;
    const int t = row & (TT - 1);
    float* S = g_s + (size_t)b * TT * TT + (size_t)t * TT;
    const int tid = threadIdx.x;
    const int lane = tid & 31, warp = tid >> 5;
    const int limit = (t & ~127) + 128;
    __shared__ float red[8];

    float v[8];
    float mx = -INFINITY;
#pragma unroll
    for (int i = 0; i < 8; i++) {
        int j = tid + i * 256;
        float s = (j <= t) ? S[j] : -INFINITY;
        v[i] = s;
        mx = fmaxf(mx, s);
    }
#pragma unroll
    for (int o = 16; o; o >>= 1) mx = fmaxf(mx, __shfl_xor_sync(0xffffffffu, mx, o));
    if (lane == 0) red[warp] = mx;
    __syncthreads();
    float bm = red[0];
#pragma unroll
    for (int w = 1; w < 8; w++) bm = fmaxf(bm, red[w]);
    __syncthreads();

    float sum = 0.f;
#pragma unroll
    for (int i = 0; i < 8; i++) {
        int j = tid + i * 256;
        float e = (j <= t) ? expf(v[i] - bm) : 0.f;
        v[i] = e;
        sum += e;
    }
#pragma unroll
    for (int o = 16; o; o >>= 1) sum += __shfl_xor_sync(0xffffffffu, sum, o);
    if (lane == 0) red[warp] = sum;
    __syncthreads();
    float tot = 0.f;
#pragma unroll
    for (int w = 0; w < 8; w++) tot += red[w];
    float inv = 1.f / tot;
#pragma unroll
    for (int i = 0; i < 8; i++) {
        int j = tid + i * 256;
        if (j < limit) S[j] = roundtf(v[i] * inv);
    }
}

// O = P Vt^T ; grid (HH/BN, TT/BM, BQ), 128 threads.
// K truncated at m0+128 (P zero beyond).
__global__ void __launch_bounds__(128) pv_kernel(float* __restrict__ out) {
    int b = blockIdx.z;
    int m0 = blockIdx.y * BM, n0 = blockIdx.x * BN;
    const float* P = g_s + (size_t)b * TT * TT;
    const float* Vt = g_vt + (size_t)b * HH * TT;
    float* C = out + (size_t)b * TT * HH;
    gemm_nt<false, false>(P, Vt, C, TT, TT, HH, m0 + BM, m0, n0, 1.0f);
}

// ---------------------------------------------------------------------------
extern "C" void kernel_launch(void* const* d_in, const int* in_sizes, int n_in,
                              void* d_out, int out_size) {
    const float* x  = (const float*)d_in[0];
    const float* Wk = (const float*)d_in[1];
    const float* Wq = (const float*)d_in[2];
    const float* Wv = (const float*)d_in[3];
    float* out = (float*)d_out;

    static int smem_set = 0;
    if (!smem_set) {
        cudaFuncSetAttribute(qkv_kernel,   cudaFuncAttributeMaxDynamicSharedMemorySize, SMEM_GEMM);
        cudaFuncSetAttribute(score_kernel, cudaFuncAttributeMaxDynamicSharedMemorySize, SMEM_GEMM);
        cudaFuncSetAttribute(pv_kernel,    cudaFuncAttributeMaxDynamicSharedMemorySize, SMEM_GEMM);
        smem_set = 1;
    }

    dim3 blk(256);
    const int X4 = (BQ * TT * EE) / 4;
    const int W4 = (HH * EE) / 4;

    round_kernel<<<X4 / 256, blk>>>((const float4*)x,  0);
    round_kernel<<<W4 / 256, blk>>>((const float4*)Wq, 1);
    round_kernel<<<W4 / 256, blk>>>((const float4*)Wk, 2);
    round_kernel<<<W4 / 256, blk>>>((const float4*)Wv, 3);

    qkv_kernel<<<dim3(HH / BN, (BQ * TT) / BM, 3), 128, SMEM_GEMM>>>();
    transpose_kernel<<<dim3(HH / 32, TT / 32, BQ), dim3(32, 8)>>>();
    score_kernel<<<dim3(TT / BN, TT / BM, BQ), 128, SMEM_GEMM>>>();
    softmax_kernel<<<dim3(BQ * TT), blk>>>();
    pv_kernel<<<dim3(HH / BN, TT / BM, BQ), 128, SMEM_GEMM>>>(out);
}

// round 14
// speedup vs baseline: 1.0851x; 1.0851x over previous
#include <cuda_runtime.h>
#include <math.h>

// Problem dims
#define BQ 8
#define TT 2048
#define EE 1024
#define HH 1024

// GEMM tile config: CTA 128x128, 8 warps (4m x 2n), warp tile 32x64,
// K staged in 32-wide chunks, 3-stage cp.async ring, ldmatrix fragments.
#define BM 128
#define BN 128
#define BKT 32
#define LDAS 36                        // 32 + 4 pad -> conflict-free LDS/LDSM
#define STG_WORDS (BM * LDAS)          // 4608 words = 18432 B per operand stage
#define STAGES 3
#define SMEM_GEMM (STAGES * 2 * STG_WORDS * 4)  // 110592 B

// Scratch (allocation-free rule: __device__ globals; device-side access ONLY —
// taking these symbols' addresses from host code was the R7 silent-zero bug)
__device__ float g_x [(long long)BQ * TT * EE];   // tf32-rounded x
__device__ float g_wq[(long long)HH * EE];        // tf32-rounded weights
__device__ float g_wk[(long long)HH * EE];
__device__ float g_wv[(long long)HH * EE];
__device__ float g_q [(long long)BQ * TT * HH];   // rounded at store
__device__ float g_k [(long long)BQ * TT * HH];
__device__ float g_v [(long long)BQ * TT * HH];
__device__ float g_vt[(long long)BQ * HH * TT];   // V transposed [b][h][s]
__device__ float g_s [(long long)BQ * TT * TT];   // scores / probs

__device__ __forceinline__ unsigned f2tf(float x) {
    unsigned r;
    asm("cvt.rna.tf32.f32 %0, %1;" : "=r"(r) : "f"(x));
    return r;
}
__device__ __forceinline__ float roundtf(float x) { return __uint_as_float(f2tf(x)); }

__device__ __forceinline__ void mma_tf32(float* c,
                                         unsigned a0, unsigned a1, unsigned a2, unsigned a3,
                                         unsigned b0, unsigned b1) {
    asm volatile(
        "mma.sync.aligned.m16n8k8.row.col.f32.tf32.tf32.f32 "
        "{%0,%1,%2,%3}, {%4,%5,%6,%7}, {%8,%9}, {%0,%1,%2,%3};"
        : "+f"(c[0]), "+f"(c[1]), "+f"(c[2]), "+f"(c[3])
        : "r"(a0), "r"(a1), "r"(a2), "r"(a3), "r"(b0), "r"(b1));
}

// ldmatrix.x4 on tf32 data: each 8x8xb16 matrix == 8x4xfp32 tile whose
// lane->(l/4, l%4) layout is exactly the m16n8k8 tf32 fragment sublayout.
__device__ __forceinline__ void ldsm4(unsigned& r0, unsigned& r1,
                                      unsigned& r2, unsigned& r3, unsigned addr) {
    asm volatile("ldmatrix.sync.aligned.m8n8.x4.shared.b16 {%0,%1,%2,%3}, [%4];"
                 : "=r"(r0), "=r"(r1), "=r"(r2), "=r"(r3) : "r"(addr));
}

__device__ __forceinline__ unsigned smem_u32(const void* p) {
    return (unsigned)__cvta_generic_to_shared(p);
}
__device__ __forceinline__ void cp_async16(unsigned dst, const void* src) {
    asm volatile("cp.async.cg.shared.global [%0], [%1], 16;" :: "r"(dst), "l"(src));
}
__device__ __forceinline__ void cp_commit() { asm volatile("cp.async.commit_group;"); }
__device__ __forceinline__ void cp_wait1()  { asm volatile("cp.async.wait_group 1;"); }

// ---------------------------------------------------------------------------
// C[M,N] = scale * A[M,K] * B[N,K]^T  (A,B row-major, K contiguous for both).
// Inputs PRE-ROUNDED to tf32. 256 threads, 8 warps (4m x 2n), warp tile
// 32x64, m16n8k8 tf32 mma. Fragments via ldmatrix.x4 (6 LDSM + 16 HMMA per
// k=8 slice, was 24 LDS + 16 HMMA). 3-stage cp.async ring, wait_group 1,
// ONE barrier per BKT=32 chunk.
// CAUSAL: store only where global col <= global row.
// ROUND:  store outputs rounded to tf32.
// ---------------------------------------------------------------------------
template <bool CAUSAL, bool ROUND>
__device__ __forceinline__ void gemm_nt(const float* __restrict__ A,
                                        const float* __restrict__ B,
                                        float* __restrict__ C,
                                        int lda, int ldb, int ldc,
                                        int K, int m0, int n0, float scale) {
    extern __shared__ unsigned sm[];

    const int tid = threadIdx.x;
    const int warp = tid >> 5, lane = tid & 31;
    const int wm = warp >> 1;  // 0..3
    const int wn = warp & 1;   // 0..1

    float acc[2][8][4];
#pragma unroll
    for (int i = 0; i < 2; i++)
#pragma unroll
        for (int j = 0; j < 8; j++)
#pragma unroll
            for (int r = 0; r < 4; r++) acc[i][j][r] = 0.f;

    // ldmatrix lane addressing: lane = 8*p + q supplies the row-q address of
    // matrix p. Word offsets within a stage (ks added per slice):
    //   A i-group: m0/m1 = rows {0-7, 8-15} at col ks; m2/m3 same rows at ks+4
    //   B jj-pair: m0/m1 = rows of j=2jj at cols {ks, ks+4}; m2/m3 = j=2jj+1
    const int p = lane >> 3, q = lane & 7;
    int aoff[2], boff[4];
#pragma unroll
    for (int i = 0; i < 2; i++)
        aoff[i] = (wm * 32 + i * 16 + (p & 1) * 8 + q) * LDAS + (p >> 1) * 4;
#pragma unroll
    for (int jj = 0; jj < 4; jj++)
        boff[jj] = (wn * 64 + jj * 16 + (p >> 1) * 8 + q) * LDAS + (p & 1) * 4;

    // Staging: 16B chunks. Per stage each operand is 128 rows x 32 words =
    // 1024 chunks; 256 threads x 4 chunks. row = chunk>>3, word = (chunk&7)*4.
    auto issue = [&](int s, int ktw) {
        unsigned* as = sm + s * 2 * STG_WORDS;
        unsigned* bs = as + STG_WORDS;
#pragma unroll
        for (int pc = 0; pc < 4; pc++) {
            int chunk = tid + 256 * pc;
            int row = chunk >> 3;
            int cw = (chunk & 7) * 4;
            cp_async16(smem_u32(&as[row * LDAS + cw]),
                       A + (size_t)(m0 + row) * lda + ktw + cw);
            cp_async16(smem_u32(&bs[row * LDAS + cw]),
                       B + (size_t)(n0 + row) * ldb + ktw + cw);
        }
        cp_commit();
    };

    const int nk = K / BKT;   // >= 4 for all call sites
    issue(0, 0);
    issue(1, BKT);

    for (int kt = 0; kt < nk; kt++) {
        cp_wait1();           // stage kt resident (kt+1 may still be in flight)
        __syncthreads();
        // Stage (kt+2)%3 was last read in iteration kt-1, which every warp
        // finished before this barrier; issue strictly after it.
        if (kt + 2 < nk) issue((kt + 2) % STAGES, (kt + 2) * BKT);

        const unsigned* as = sm + (kt % STAGES) * 2 * STG_WORDS;
        const unsigned* bs = as + STG_WORDS;
        const unsigned abase = smem_u32(as);
        const unsigned bbase = smem_u32(bs);

#pragma unroll
        for (int ks = 0; ks < BKT; ks += 8) {
            unsigned a[2][4], b[8][2];
            ldsm4(a[0][0], a[0][1], a[0][2], a[0][3], abase + (aoff[0] + ks) * 4);
            ldsm4(a[1][0], a[1][1], a[1][2], a[1][3], abase + (aoff[1] + ks) * 4);
            ldsm4(b[0][0], b[0][1], b[1][0], b[1][1], bbase + (boff[0] + ks) * 4);
            ldsm4(b[2][0], b[2][1], b[3][0], b[3][1], bbase + (boff[1] + ks) * 4);
            ldsm4(b[4][0], b[4][1], b[5][0], b[5][1], bbase + (boff[2] + ks) * 4);
            ldsm4(b[6][0], b[6][1], b[7][0], b[7][1], bbase + (boff[3] + ks) * 4);
#pragma unroll
            for (int i = 0; i < 2; i++)
#pragma unroll
                for (int j = 0; j < 8; j++)
                    mma_tf32(acc[i][j], a[i][0], a[i][1], a[i][2], a[i][3],
                             b[j][0], b[j][1]);
        }
    }

#pragma unroll
    for (int i = 0; i < 2; i++) {
        int rbase = m0 + wm * 32 + i * 16 + (lane >> 2);
#pragma unroll
        for (int j = 0; j < 8; j++) {
            int cn = n0 + wn * 64 + j * 8 + (lane & 3) * 2;
#pragma unroll
            for (int h = 0; h < 2; h++) {
                int r = rbase + h * 8;
                float v0 = acc[i][j][2 * h + 0] * scale;
                float v1 = acc[i][j][2 * h + 1] * scale;
                if (ROUND) { v0 = roundtf(v0); v1 = roundtf(v1); }
                if (CAUSAL) {
                    if (cn <= r)     C[(size_t)r * ldc + cn]     = v0;
                    if (cn + 1 <= r) C[(size_t)r * ldc + cn + 1] = v1;
                } else {
                    *reinterpret_cast<float2*>(C + (size_t)r * ldc + cn) =
                        make_float2(v0, v1);
                }
            }
        }
    }
}

// ---------------------------------------------------------------------------
// Kernels
// ---------------------------------------------------------------------------

// tf32 pre-round; dst selected DEVICE-SIDE.
__global__ void __launch_bounds__(256) round_kernel(const float4* __restrict__ src,
                                                    int which) {
    float4* dst;
    switch (which) {
        case 0:  dst = reinterpret_cast<float4*>(g_x);  break;
        case 1:  dst = reinterpret_cast<float4*>(g_wq); break;
        case 2:  dst = reinterpret_cast<float4*>(g_wk); break;
        default: dst = reinterpret_cast<float4*>(g_wv); break;
    }
    int i = blockIdx.x * 256 + threadIdx.x;
    float4 v = src[i];
    dst[i] = make_float4(roundtf(v.x), roundtf(v.y), roundtf(v.z), roundtf(v.w));
}

// Q/K/V = x @ W^T ; grid (HH/BN, (BQ*TT)/BM, 3)
__global__ void __launch_bounds__(256) qkv_kernel() {
    const float* W;
    float* out;
    switch (blockIdx.z) {
        case 0: W = g_wq; out = g_q; break;
        case 1: W = g_wk; out = g_k; break;
        default: W = g_wv; out = g_v; break;
    }
    gemm_nt<false, true>(g_x, W, out, EE, EE, HH, EE,
                         blockIdx.y * BM, blockIdx.x * BN, 1.0f);
}

// Vt[b][h][s] = V[b][s][h] ; grid (HH/32, TT/32, BQ), block (32, 8)
__global__ void __launch_bounds__(256) transpose_kernel() {
    __shared__ float tile[32][33];
    const int b = blockIdx.z;
    const float* src = g_v + (size_t)b * TT * HH;
    float* dst = g_vt + (size_t)b * HH * TT;
    const int h0 = blockIdx.x * 32, s0 = blockIdx.y * 32;
    const int tx = threadIdx.x, ty = threadIdx.y;
#pragma unroll
    for (int i = 0; i < 4; i++)
        tile[ty + 8 * i][tx] = src[(size_t)(s0 + ty + 8 * i) * HH + h0 + tx];
    __syncthreads();
#pragma unroll
    for (int i = 0; i < 4; i++)
        dst[(size_t)(h0 + ty + 8 * i) * TT + s0 + tx] = tile[tx][ty + 8 * i];
}

// S = (Q K^T) * E^-0.5, causal; grid (TT/BN, TT/BM, BQ)
__global__ void __launch_bounds__(256) score_kernel() {
    int b = blockIdx.z;
    int m0 = blockIdx.y * BM, n0 = blockIdx.x * BN;
    if (n0 > m0) return;  // tile entirely above the diagonal -> never read
    const float* Q = g_q + (size_t)b * TT * HH;
    const float* Kp = g_k + (size_t)b * TT * HH;
    float* S = g_s + (size_t)b * TT * TT;
    gemm_nt<true, false>(Q, Kp, S, HH, HH, TT, HH, m0, n0, 0.03125f);  // 1024^-0.5
}

// Row-wise causal softmax in place on g_s; stores tf32-rounded P.
// Zero-fills only up to the 128-rounded boundary pv reads. grid (BQ*TT)
__global__ void __launch_bounds__(256) softmax_kernel() {
    const int row = blockIdx.x;
    const int b = row >> 11;
    const int t = row & (TT - 1);
    float* S = g_s + (size_t)b * TT * TT + (size_t)t * TT;
    const int tid = threadIdx.x;
    const int lane = tid & 31, warp = tid >> 5;
    const int limit = (t & ~127) + 128;
    __shared__ float red[8];

    float v[8];
    float mx = -INFINITY;
#pragma unroll
    for (int i = 0; i < 8; i++) {
        int j = tid + i * 256;
        float s = (j <= t) ? S[j] : -INFINITY;
        v[i] = s;
        mx = fmaxf(mx, s);
    }
#pragma unroll
    for (int o = 16; o; o >>= 1) mx = fmaxf(mx, __shfl_xor_sync(0xffffffffu, mx, o));
    if (lane == 0) red[warp] = mx;
    __syncthreads();
    float bm = red[0];
#pragma unroll
    for (int w = 1; w < 8; w++) bm = fmaxf(bm, red[w]);
    __syncthreads();

    float sum = 0.f;
#pragma unroll
    for (int i = 0; i < 8; i++) {
        int j = tid + i * 256;
        float e = (j <= t) ? expf(v[i] - bm) : 0.f;
        v[i] = e;
        sum += e;
    }
#pragma unroll
    for (int o = 16; o; o >>= 1) sum += __shfl_xor_sync(0xffffffffu, sum, o);
    if (lane == 0) red[warp] = sum;
    __syncthreads();
    float tot = 0.f;
#pragma unroll
    for (int w = 0; w < 8; w++) tot += red[w];
    float inv = 1.f / tot;
#pragma unroll
    for (int i = 0; i < 8; i++) {
        int j = tid + i * 256;
        if (j < limit) S[j] = roundtf(v[i] * inv);
    }
}

// O = P Vt^T ; grid (HH/BN, TT/BM, BQ). K truncated at m0+128 (P zero beyond).
__global__ void __launch_bounds__(256) pv_kernel(float* __restrict__ out) {
    int b = blockIdx.z;
    int m0 = blockIdx.y * BM, n0 = blockIdx.x * BN;
    const float* P = g_s + (size_t)b * TT * TT;
    const float* Vt = g_vt + (size_t)b * HH * TT;
    float* C = out + (size_t)b * TT * HH;
    gemm_nt<false, false>(P, Vt, C, TT, TT, HH, m0 + BM, m0, n0, 1.0f);
}

// ---------------------------------------------------------------------------
extern "C" void kernel_launch(void* const* d_in, const int* in_sizes, int n_in,
                              void* d_out, int out_size) {
    const float* x  = (const float*)d_in[0];
    const float* Wk = (const float*)d_in[1];
    const float* Wq = (const float*)d_in[2];
    const float* Wv = (const float*)d_in[3];
    float* out = (float*)d_out;

    static int smem_set = 0;
    if (!smem_set) {
        cudaFuncSetAttribute(qkv_kernel,   cudaFuncAttributeMaxDynamicSharedMemorySize, SMEM_GEMM);
        cudaFuncSetAttribute(score_kernel, cudaFuncAttributeMaxDynamicSharedMemorySize, SMEM_GEMM);
        cudaFuncSetAttribute(pv_kernel,    cudaFuncAttributeMaxDynamicSharedMemorySize, SMEM_GEMM);
        smem_set = 1;
    }

    dim3 blk(256);
    const int X4 = (BQ * TT * EE) / 4;
    const int W4 = (HH * EE) / 4;

    round_kernel<<<X4 / 256, blk>>>((const float4*)x,  0);
    round_kernel<<<W4 / 256, blk>>>((const float4*)Wq, 1);
    round_kernel<<<W4 / 256, blk>>>((const float4*)Wk, 2);
    round_kernel<<<W4 / 256, blk>>>((const float4*)Wv, 3);

    qkv_kernel<<<dim3(HH / BN, (BQ * TT) / BM, 3), blk, SMEM_GEMM>>>();
    transpose_kernel<<<dim3(HH / 32, TT / 32, BQ), dim3(32, 8)>>>();
    score_kernel<<<dim3(TT / BN, TT / BM, BQ), blk, SMEM_GEMM>>>();
    softmax_kernel<<<dim3(BQ * TT), blk>>>();
    pv_kernel<<<dim3(HH / BN, TT / BM, BQ), blk, SMEM_GEMM>>>(out);
}

// round 15
// speedup vs baseline: 1.7674x; 1.6288x over previous
#include <cuda_runtime.h>
#include <cuda_fp16.h>
#include <math.h>
#include <type_traits>

// Problem dims
#define BQ 8
#define TT 2048
#define EE 1024
#define HH 1024

// GEMM tile config: CTA 128x128, 8 warps (4m x 2n), warp tile 32x64,
// fp16 m16n8k16 mma, K staged in 64-wide chunks, 3-stage cp.async ring.
#define BM 128
#define BN 128
#define BKT 64
#define LDASH 72                        // 64 + 8 pad (halves); 144B rows -> /16=9,
                                        // odd => conflict-free ldmatrix + staging
#define STG_HALVES (BM * LDASH)         // 9216 halves = 18432 B per operand stage
#define STAGES 3
#define SMEM_GEMM (STAGES * 2 * STG_HALVES * 2)  // 110592 B -> 2 CTAs/SM

// Scratch (allocation-free rule: __device__ globals; device-side access ONLY —
// taking these symbols' addresses from host code was the R7 silent-zero bug)
__device__ __half g_x [(long long)BQ * TT * EE];   // fp16 x
__device__ __half g_wq[(long long)HH * EE];        // fp16 weights
__device__ __half g_wk[(long long)HH * EE];
__device__ __half g_wv[(long long)HH * EE];
__device__ __half g_q [(long long)BQ * TT * HH];   // fp16 Q/K/V
__device__ __half g_k [(long long)BQ * TT * HH];
__device__ __half g_v [(long long)BQ * TT * HH];
__device__ __half g_vt[(long long)BQ * HH * TT];   // V transposed [b][h][s]
__device__ float  g_s [(long long)BQ * TT * TT];   // raw scores (fp32 for softmax)
__device__ __half g_p [(long long)BQ * TT * TT];   // probabilities (fp16)

__device__ __forceinline__ void mma_f16(float* c,
                                        unsigned a0, unsigned a1, unsigned a2, unsigned a3,
                                        unsigned b0, unsigned b1) {
    asm volatile(
        "mma.sync.aligned.m16n8k16.row.col.f32.f16.f16.f32 "
        "{%0,%1,%2,%3}, {%4,%5,%6,%7}, {%8,%9}, {%0,%1,%2,%3};"
        : "+f"(c[0]), "+f"(c[1]), "+f"(c[2]), "+f"(c[3])
        : "r"(a0), "r"(a1), "r"(a2), "r"(a3), "r"(b0), "r"(b1));
}

__device__ __forceinline__ void ldsm4(unsigned& r0, unsigned& r1,
                                      unsigned& r2, unsigned& r3, unsigned addr) {
    asm volatile("ldmatrix.sync.aligned.m8n8.x4.shared.b16 {%0,%1,%2,%3}, [%4];"
                 : "=r"(r0), "=r"(r1), "=r"(r2), "=r"(r3) : "r"(addr));
}

__device__ __forceinline__ unsigned smem_u32(const void* p) {
    return (unsigned)__cvta_generic_to_shared(p);
}
__device__ __forceinline__ void cp_async16(unsigned dst, const void* src) {
    asm volatile("cp.async.cg.shared.global [%0], [%1], 16;" :: "r"(dst), "l"(src));
}
__device__ __forceinline__ void cp_commit() { asm volatile("cp.async.commit_group;"); }
__device__ __forceinline__ void cp_wait1()  { asm volatile("cp.async.wait_group 1;"); }
__device__ __forceinline__ void cp_wait0()  { asm volatile("cp.async.wait_group 0;"); }

// ---------------------------------------------------------------------------
// C[M,N] = scale * A[M,K] * B[N,K]^T   (A,B fp16 row-major, K contiguous).
// 256 threads, 8 warps (4m x 2n), warp tile 32x64, m16n8k16 fp16 mma with
// fp32 accumulators. Fragments via ldmatrix.x4 (6 LDSM + 16 HMMA per k=16
// slice). 3-stage cp.async ring, ONE barrier per BKT=64 chunk; wait_group 0
// on the final chunk (wait_group 1 there would leave the last stage
// formally unguaranteed).
// OutT=__half: plain half2 stores. OutT=float: float2, or causal-predicated
// scalars when CAUSAL.
// ---------------------------------------------------------------------------
template <bool CAUSAL, typename OutT>
__device__ __forceinline__ void gemm_nt(const __half* __restrict__ A,
                                        const __half* __restrict__ B,
                                        OutT* __restrict__ C,
                                        int lda, int ldb, int ldc,
                                        int K, int m0, int n0, float scale) {
    extern __shared__ __half smh[];

    const int tid = threadIdx.x;
    const int warp = tid >> 5, lane = tid & 31;
    const int wm = warp >> 1;  // 0..3
    const int wn = warp & 1;   // 0..1

    float acc[2][8][4];
#pragma unroll
    for (int i = 0; i < 2; i++)
#pragma unroll
        for (int j = 0; j < 8; j++)
#pragma unroll
            for (int r = 0; r < 4; r++) acc[i][j][r] = 0.f;

    // ldmatrix lane addressing (lane = 8p+q supplies row-q address of matrix p).
    // A x4 (16x16): m0=rows/k0, m1=rows+8/k0, m2=rows/k+8, m3=rows+8/k+8
    //   -> row = base + (p&1)*8 + q, col = ks + (p>>1)*8
    // B x4 (two n-groups x two k-halves): m0=n/k0, m1=n/k+8, m2=n+8/k0, m3=n+8/k+8
    //   -> row = base + (p>>1)*8 + q, col = ks + (p&1)*8
    const int p = lane >> 3, q = lane & 7;
    int aoff[2], boff[4];
#pragma unroll
    for (int i = 0; i < 2; i++)
        aoff[i] = (wm * 32 + i * 16 + (p & 1) * 8 + q) * LDASH + (p >> 1) * 8;
#pragma unroll
    for (int jj = 0; jj < 4; jj++)
        boff[jj] = (wn * 64 + jj * 16 + (p >> 1) * 8 + q) * LDASH + (p & 1) * 8;

    // Staging: per stage each operand is 128 rows x 64 halves (128B) =
    // 1024 16B-chunks; 256 threads x 4. row = chunk>>3, halves = (chunk&7)*8.
    auto issue = [&](int s, int ktw) {
        __half* as = smh + s * 2 * STG_HALVES;
        __half* bs = as + STG_HALVES;
#pragma unroll
        for (int pc = 0; pc < 4; pc++) {
            int chunk = tid + 256 * pc;
            int row = chunk >> 3;
            int cw = (chunk & 7) * 8;
            cp_async16(smem_u32(&as[row * LDASH + cw]),
                       A + (size_t)(m0 + row) * lda + ktw + cw);
            cp_async16(smem_u32(&bs[row * LDASH + cw]),
                       B + (size_t)(n0 + row) * ldb + ktw + cw);
        }
        cp_commit();
    };

    const int nk = K / BKT;   // >= 2 for all call sites
    issue(0, 0);
    if (nk > 1) issue(1, BKT);

    for (int kt = 0; kt < nk; kt++) {
        if (kt == nk - 1) cp_wait0(); else cp_wait1();
        __syncthreads();
        // Stage (kt+2)%3 was last read in iteration kt-1, finished by every
        // warp before this barrier; issue strictly after it.
        if (kt + 2 < nk) issue((kt + 2) % STAGES, (kt + 2) * BKT);

        const __half* as = smh + (kt % STAGES) * 2 * STG_HALVES;
        const __half* bs = as + STG_HALVES;
        const unsigned abase = smem_u32(as);
        const unsigned bbase = smem_u32(bs);

#pragma unroll
        for (int ks = 0; ks < BKT; ks += 16) {
            unsigned a[2][4], b[8][2];
            ldsm4(a[0][0], a[0][1], a[0][2], a[0][3], abase + (aoff[0] + ks) * 2);
            ldsm4(a[1][0], a[1][1], a[1][2], a[1][3], abase + (aoff[1] + ks) * 2);
            ldsm4(b[0][0], b[0][1], b[1][0], b[1][1], bbase + (boff[0] + ks) * 2);
            ldsm4(b[2][0], b[2][1], b[3][0], b[3][1], bbase + (boff[1] + ks) * 2);
            ldsm4(b[4][0], b[4][1], b[5][0], b[5][1], bbase + (boff[2] + ks) * 2);
            ldsm4(b[6][0], b[6][1], b[7][0], b[7][1], bbase + (boff[3] + ks) * 2);
#pragma unroll
            for (int i = 0; i < 2; i++)
#pragma unroll
                for (int j = 0; j < 8; j++)
                    mma_f16(acc[i][j], a[i][0], a[i][1], a[i][2], a[i][3],
                            b[j][0], b[j][1]);
        }
    }

#pragma unroll
    for (int i = 0; i < 2; i++) {
        int rbase = m0 + wm * 32 + i * 16 + (lane >> 2);
#pragma unroll
        for (int j = 0; j < 8; j++) {
            int cn = n0 + wn * 64 + j * 8 + (lane & 3) * 2;
#pragma unroll
            for (int h = 0; h < 2; h++) {
                int r = rbase + h * 8;
                float v0 = acc[i][j][2 * h + 0] * scale;
                float v1 = acc[i][j][2 * h + 1] * scale;
                if constexpr (std::is_same<OutT, __half>::value) {
                    *reinterpret_cast<__half2*>(C + (size_t)r * ldc + cn) =
                        __floats2half2_rn(v0, v1);
                } else if constexpr (CAUSAL) {
                    if (cn <= r)     C[(size_t)r * ldc + cn]     = v0;
                    if (cn + 1 <= r) C[(size_t)r * ldc + cn + 1] = v1;
                } else {
                    *reinterpret_cast<float2*>(C + (size_t)r * ldc + cn) =
                        make_float2(v0, v1);
                }
            }
        }
    }
}

// ---------------------------------------------------------------------------
// Kernels
// ---------------------------------------------------------------------------

// fp32 -> fp16 pre-convert; dst selected DEVICE-SIDE.
__global__ void __launch_bounds__(256) tohalf_kernel(const float4* __restrict__ src,
                                                     int which) {
    __half2* dst;
    switch (which) {
        case 0:  dst = reinterpret_cast<__half2*>(g_x);  break;
        case 1:  dst = reinterpret_cast<__half2*>(g_wq); break;
        case 2:  dst = reinterpret_cast<__half2*>(g_wk); break;
        default: dst = reinterpret_cast<__half2*>(g_wv); break;
    }
    int i = blockIdx.x * 256 + threadIdx.x;
    float4 v = src[i];
    dst[2 * i]     = __floats2half2_rn(v.x, v.y);
    dst[2 * i + 1] = __floats2half2_rn(v.z, v.w);
}

// Q/K/V = x @ W^T ; grid (HH/BN, (BQ*TT)/BM, 3)
__global__ void __launch_bounds__(256) qkv_kernel() {
    const __half* W;
    __half* out;
    switch (blockIdx.z) {
        case 0: W = g_wq; out = g_q; break;
        case 1: W = g_wk; out = g_k; break;
        default: W = g_wv; out = g_v; break;
    }
    gemm_nt<false>(g_x, W, out, EE, EE, HH, EE,
                   (int)blockIdx.y * BM, (int)blockIdx.x * BN, 1.0f);
}

// Vt[b][h][s] = V[b][s][h] ; grid (HH/32, TT/32, BQ), block (32, 8)
__global__ void __launch_bounds__(256) transpose_kernel() {
    __shared__ float tile[32][33];
    const int b = blockIdx.z;
    const __half* src = g_v + (size_t)b * TT * HH;
    __half* dst = g_vt + (size_t)b * HH * TT;
    const int h0 = blockIdx.x * 32, s0 = blockIdx.y * 32;
    const int tx = threadIdx.x, ty = threadIdx.y;
#pragma unroll
    for (int i = 0; i < 4; i++)
        tile[ty + 8 * i][tx] =
            __half2float(src[(size_t)(s0 + ty + 8 * i) * HH + h0 + tx]);
    __syncthreads();
#pragma unroll
    for (int i = 0; i < 4; i++)
        dst[(size_t)(h0 + ty + 8 * i) * TT + s0 + tx] =
            __float2half_rn(tile[tx][ty + 8 * i]);  // exact round-trip
}

// S = (Q K^T) * E^-0.5 (fp32 out), causal; grid (TT/BN, TT/BM, BQ)
__global__ void __launch_bounds__(256) score_kernel() {
    int b = blockIdx.z;
    int m0 = blockIdx.y * BM, n0 = blockIdx.x * BN;
    if (n0 > m0) return;  // tile entirely above the diagonal -> never read
    const __half* Q = g_q + (size_t)b * TT * HH;
    const __half* Kp = g_k + (size_t)b * TT * HH;
    float* S = g_s + (size_t)b * TT * TT;
    gemm_nt<true>(Q, Kp, S, HH, HH, TT, HH, m0, n0, 0.03125f);  // 1024^-0.5
}

// Row-wise causal softmax: reads fp32 S, writes fp16 P.
// Zero-fills only up to the 128-rounded boundary pv reads. grid (BQ*TT)
__global__ void __launch_bounds__(256) softmax_kernel() {
    const int row = blockIdx.x;
    const int b = row >> 11;
    const int t = row & (TT - 1);
    const float* S = g_s + (size_t)b * TT * TT + (size_t)t * TT;
    __half* P = g_p + (size_t)b * TT * TT + (size_t)t * TT;
    const int tid = threadIdx.x;
    const int lane = tid & 31, warp = tid >> 5;
    const int limit = (t & ~127) + 128;
    __shared__ float red[8];

    float v[8];
    float mx = -INFINITY;
#pragma unroll
    for (int i = 0; i < 8; i++) {
        int j = tid + i * 256;
        float s = (j <= t) ? S[j] : -INFINITY;
        v[i] = s;
        mx = fmaxf(mx, s);
    }
#pragma unroll
    for (int o = 16; o; o >>= 1) mx = fmaxf(mx, __shfl_xor_sync(0xffffffffu, mx, o));
    if (lane == 0) red[warp] = mx;
    __syncthreads();
    float bm = red[0];
#pragma unroll
    for (int w = 1; w < 8; w++) bm = fmaxf(bm, red[w]);
    __syncthreads();

    float sum = 0.f;
#pragma unroll
    for (int i = 0; i < 8; i++) {
        int j = tid + i * 256;
        float e = (j <= t) ? expf(v[i] - bm) : 0.f;
        v[i] = e;
        sum += e;
    }
#pragma unroll
    for (int o = 16; o; o >>= 1) sum += __shfl_xor_sync(0xffffffffu, sum, o);
    if (lane == 0) red[warp] = sum;
    __syncthreads();
    float tot = 0.f;
#pragma unroll
    for (int w = 0; w < 8; w++) tot += red[w];
    float inv = 1.f / tot;
#pragma unroll
    for (int i = 0; i < 8; i++) {
        int j = tid + i * 256;
        if (j < limit) P[j] = __float2half_rn(v[i] * inv);
    }
}

// O = P Vt^T ; grid (HH/BN, TT/BM, BQ). K truncated at m0+128 (P zero beyond).
__global__ void __launch_bounds__(256) pv_kernel(float* __restrict__ out) {
    int b = blockIdx.z;
    int m0 = blockIdx.y * BM, n0 = blockIdx.x * BN;
    const __half* P = g_p + (size_t)b * TT * TT;
    const __half* Vt = g_vt + (size_t)b * HH * TT;
    float* C = out + (size_t)b * TT * HH;
    gemm_nt<false>(P, Vt, C, TT, TT, HH, m0 + BM, m0, n0, 1.0f);
}

// ---------------------------------------------------------------------------
extern "C" void kernel_launch(void* const* d_in, const int* in_sizes, int n_in,
                              void* d_out, int out_size) {
    const float* x  = (const float*)d_in[0];
    const float* Wk = (const float*)d_in[1];
    const float* Wq = (const float*)d_in[2];
    const float* Wv = (const float*)d_in[3];
    float* out = (float*)d_out;

    static int smem_set = 0;
    if (!smem_set) {
        cudaFuncSetAttribute(qkv_kernel,   cudaFuncAttributeMaxDynamicSharedMemorySize, SMEM_GEMM);
        cudaFuncSetAttribute(score_kernel, cudaFuncAttributeMaxDynamicSharedMemorySize, SMEM_GEMM);
        cudaFuncSetAttribute(pv_kernel,    cudaFuncAttributeMaxDynamicSharedMemorySize, SMEM_GEMM);
        smem_set = 1;
    }

    dim3 blk(256);
    const int X4 = (BQ * TT * EE) / 4;
    const int W4 = (HH * EE) / 4;

    tohalf_kernel<<<X4 / 256, blk>>>((const float4*)x,  0);
    tohalf_kernel<<<W4 / 256, blk>>>((const float4*)Wq, 1);
    tohalf_kernel<<<W4 / 256, blk>>>((const float4*)Wk, 2);
    tohalf_kernel<<<W4 / 256, blk>>>((const float4*)Wv, 3);

    qkv_kernel<<<dim3(HH / BN, (BQ * TT) / BM, 3), blk, SMEM_GEMM>>>();
    transpose_kernel<<<dim3(HH / 32, TT / 32, BQ), dim3(32, 8)>>>();
    score_kernel<<<dim3(TT / BN, TT / BM, BQ), blk, SMEM_GEMM>>>();
    softmax_kernel<<<dim3(BQ * TT), blk>>>();
    pv_kernel<<<dim3(HH / BN, TT / BM, BQ), blk, SMEM_GEMM>>>(out);
}

// round 16
// speedup vs baseline: 1.7982x; 1.0174x over previous
#include <cuda_runtime.h>
#include <cuda_fp16.h>
#include <math.h>
#include <type_traits>

// Problem dims
#define BQ 8
#define TT 2048
#define EE 1024
#define HH 1024

// GEMM tile config: CTA 128x128, 8 warps (4m x 2n), warp tile 32x64,
// fp16 m16n8k16 mma, K staged in 64-wide chunks, 3-stage cp.async ring.
#define BM 128
#define BN 128
#define BKT 64
#define LDASH 72                        // 64 + 8 pad (halves); 144B rows -> /16=9,
                                        // odd => conflict-free ldmatrix + staging
#define STG_HALVES (BM * LDASH)         // 9216 halves = 18432 B per operand stage
#define STAGES 3
#define SMEM_GEMM (STAGES * 2 * STG_HALVES * 2)  // 110592 B -> 2 CTAs/SM

// Scratch (allocation-free rule: __device__ globals; device-side access ONLY —
// taking these symbols' addresses from host code was the R7 silent-zero bug)
__device__ __half g_x [(long long)BQ * TT * EE];   // fp16 x
__device__ __half g_wq[(long long)HH * EE];        // fp16 weights
__device__ __half g_wk[(long long)HH * EE];
__device__ __half g_wv[(long long)HH * EE];
__device__ __half g_q [(long long)BQ * TT * HH];   // fp16 Q/K/V
__device__ __half g_k [(long long)BQ * TT * HH];
__device__ __half g_v [(long long)BQ * TT * HH];
__device__ __half g_vt[(long long)BQ * HH * TT];   // V transposed [b][h][s]
__device__ float  g_s [(long long)BQ * TT * TT];   // raw scores (fp32 for softmax)
__device__ __half g_p [(long long)BQ * TT * TT];   // probabilities (fp16)

__device__ __forceinline__ void mma_f16(float* c,
                                        unsigned a0, unsigned a1, unsigned a2, unsigned a3,
                                        unsigned b0, unsigned b1) {
    asm volatile(
        "mma.sync.aligned.m16n8k16.row.col.f32.f16.f16.f32 "
        "{%0,%1,%2,%3}, {%4,%5,%6,%7}, {%8,%9}, {%0,%1,%2,%3};"
        : "+f"(c[0]), "+f"(c[1]), "+f"(c[2]), "+f"(c[3])
        : "r"(a0), "r"(a1), "r"(a2), "r"(a3), "r"(b0), "r"(b1));
}

__device__ __forceinline__ void ldsm4(unsigned& r0, unsigned& r1,
                                      unsigned& r2, unsigned& r3, unsigned addr) {
    asm volatile("ldmatrix.sync.aligned.m8n8.x4.shared.b16 {%0,%1,%2,%3}, [%4];"
                 : "=r"(r0), "=r"(r1), "=r"(r2), "=r"(r3) : "r"(addr));
}

__device__ __forceinline__ unsigned smem_u32(const void* p) {
    return (unsigned)__cvta_generic_to_shared(p);
}
__device__ __forceinline__ void cp_async16(unsigned dst, const void* src) {
    asm volatile("cp.async.cg.shared.global [%0], [%1], 16;" :: "r"(dst), "l"(src));
}
__device__ __forceinline__ void cp_commit() { asm volatile("cp.async.commit_group;"); }
__device__ __forceinline__ void cp_wait1()  { asm volatile("cp.async.wait_group 1;"); }
__device__ __forceinline__ void cp_wait0()  { asm volatile("cp.async.wait_group 0;"); }

// ---------------------------------------------------------------------------
// C[M,N] = scale * A[M,K] * B[N,K]^T   (A,B fp16 row-major, K contiguous).
// 256 threads, 8 warps (4m x 2n), warp tile 32x64, m16n8k16 fp16 mma with
// fp32 accumulators. Fragments via ldmatrix.x4. 3-stage cp.async ring, ONE
// barrier per BKT=64 chunk; wait_group 0 on the final chunk.
// CAUSAL: per-element col<=row predicated stores (diagonal tiles only).
// OutT=__half: half2 stores. OutT=float (non-causal): float2 stores.
// ---------------------------------------------------------------------------
template <bool CAUSAL, typename OutT>
__device__ __forceinline__ void gemm_nt(const __half* __restrict__ A,
                                        const __half* __restrict__ B,
                                        OutT* __restrict__ C,
                                        int lda, int ldb, int ldc,
                                        int K, int m0, int n0, float scale) {
    extern __shared__ __half smh[];

    const int tid = threadIdx.x;
    const int warp = tid >> 5, lane = tid & 31;
    const int wm = warp >> 1;  // 0..3
    const int wn = warp & 1;   // 0..1

    float acc[2][8][4];
#pragma unroll
    for (int i = 0; i < 2; i++)
#pragma unroll
        for (int j = 0; j < 8; j++)
#pragma unroll
            for (int r = 0; r < 4; r++) acc[i][j][r] = 0.f;

    // ldmatrix lane addressing (lane = 8p+q supplies row-q address of matrix p).
    const int p = lane >> 3, q = lane & 7;
    int aoff[2], boff[4];
#pragma unroll
    for (int i = 0; i < 2; i++)
        aoff[i] = (wm * 32 + i * 16 + (p & 1) * 8 + q) * LDASH + (p >> 1) * 8;
#pragma unroll
    for (int jj = 0; jj < 4; jj++)
        boff[jj] = (wn * 64 + jj * 16 + (p >> 1) * 8 + q) * LDASH + (p & 1) * 8;

    // Staging: per stage each operand is 128 rows x 64 halves (128B) =
    // 1024 16B-chunks; 256 threads x 4. row = chunk>>3, halves = (chunk&7)*8.
    auto issue = [&](int s, int ktw) {
        __half* as = smh + s * 2 * STG_HALVES;
        __half* bs = as + STG_HALVES;
#pragma unroll
        for (int pc = 0; pc < 4; pc++) {
            int chunk = tid + 256 * pc;
            int row = chunk >> 3;
            int cw = (chunk & 7) * 8;
            cp_async16(smem_u32(&as[row * LDASH + cw]),
                       A + (size_t)(m0 + row) * lda + ktw + cw);
            cp_async16(smem_u32(&bs[row * LDASH + cw]),
                       B + (size_t)(n0 + row) * ldb + ktw + cw);
        }
        cp_commit();
    };

    const int nk = K / BKT;   // >= 2 for all call sites
    issue(0, 0);
    if (nk > 1) issue(1, BKT);

    for (int kt = 0; kt < nk; kt++) {
        if (kt == nk - 1) cp_wait0(); else cp_wait1();
        __syncthreads();
        // Stage (kt+2)%3 was last read in iteration kt-1, finished by every
        // warp before this barrier; issue strictly after it.
        if (kt + 2 < nk) issue((kt + 2) % STAGES, (kt + 2) * BKT);

        const __half* as = smh + (kt % STAGES) * 2 * STG_HALVES;
        const __half* bs = as + STG_HALVES;
        const unsigned abase = smem_u32(as);
        const unsigned bbase = smem_u32(bs);

#pragma unroll
        for (int ks = 0; ks < BKT; ks += 16) {
            unsigned a[2][4], b[8][2];
            ldsm4(a[0][0], a[0][1], a[0][2], a[0][3], abase + (aoff[0] + ks) * 2);
            ldsm4(a[1][0], a[1][1], a[1][2], a[1][3], abase + (aoff[1] + ks) * 2);
            ldsm4(b[0][0], b[0][1], b[1][0], b[1][1], bbase + (boff[0] + ks) * 2);
            ldsm4(b[2][0], b[2][1], b[3][0], b[3][1], bbase + (boff[1] + ks) * 2);
            ldsm4(b[4][0], b[4][1], b[5][0], b[5][1], bbase + (boff[2] + ks) * 2);
            ldsm4(b[6][0], b[6][1], b[7][0], b[7][1], bbase + (boff[3] + ks) * 2);
#pragma unroll
            for (int i = 0; i < 2; i++)
#pragma unroll
                for (int j = 0; j < 8; j++)
                    mma_f16(acc[i][j], a[i][0], a[i][1], a[i][2], a[i][3],
                            b[j][0], b[j][1]);
        }
    }

#pragma unroll
    for (int i = 0; i < 2; i++) {
        int rbase = m0 + wm * 32 + i * 16 + (lane >> 2);
#pragma unroll
        for (int j = 0; j < 8; j++) {
            int cn = n0 + wn * 64 + j * 8 + (lane & 3) * 2;
#pragma unroll
            for (int h = 0; h < 2; h++) {
                int r = rbase + h * 8;
                float v0 = acc[i][j][2 * h + 0] * scale;
                float v1 = acc[i][j][2 * h + 1] * scale;
                if constexpr (std::is_same<OutT, __half>::value) {
                    *reinterpret_cast<__half2*>(C + (size_t)r * ldc + cn) =
                        __floats2half2_rn(v0, v1);
                } else if constexpr (CAUSAL) {
                    if (cn <= r)     C[(size_t)r * ldc + cn]     = v0;
                    if (cn + 1 <= r) C[(size_t)r * ldc + cn + 1] = v1;
                } else {
                    *reinterpret_cast<float2*>(C + (size_t)r * ldc + cn) =
                        make_float2(v0, v1);
                }
            }
        }
    }
}

// ---------------------------------------------------------------------------
// Kernels
// ---------------------------------------------------------------------------

// fp32 -> fp16 pre-convert; dst selected DEVICE-SIDE.
__global__ void __launch_bounds__(256) tohalf_kernel(const float4* __restrict__ src,
                                                     int which) {
    __half2* dst;
    switch (which) {
        case 0:  dst = reinterpret_cast<__half2*>(g_x);  break;
        case 1:  dst = reinterpret_cast<__half2*>(g_wq); break;
        case 2:  dst = reinterpret_cast<__half2*>(g_wk); break;
        default: dst = reinterpret_cast<__half2*>(g_wv); break;
    }
    int i = blockIdx.x * 256 + threadIdx.x;
    float4 v = src[i];
    dst[2 * i]     = __floats2half2_rn(v.x, v.y);
    dst[2 * i + 1] = __floats2half2_rn(v.z, v.w);
}

// Q/K/V = x @ W^T ; grid (HH/BN, (BQ*TT)/BM, 3)
__global__ void __launch_bounds__(256) qkv_kernel() {
    const __half* W;
    __half* out;
    switch (blockIdx.z) {
        case 0: W = g_wq; out = g_q; break;
        case 1: W = g_wk; out = g_k; break;
        default: W = g_wv; out = g_v; break;
    }
    gemm_nt<false>(g_x, W, out, EE, EE, HH, EE,
                   (int)blockIdx.y * BM, (int)blockIdx.x * BN, 1.0f);
}

// Vt[b][h][s] = V[b][s][h] ; grid (HH/32, TT/32, BQ), block (32, 8)
__global__ void __launch_bounds__(256) transpose_kernel() {
    __shared__ float tile[32][33];
    const int b = blockIdx.z;
    const __half* src = g_v + (size_t)b * TT * HH;
    __half* dst = g_vt + (size_t)b * HH * TT;
    const int h0 = blockIdx.x * 32, s0 = blockIdx.y * 32;
    const int tx = threadIdx.x, ty = threadIdx.y;
#pragma unroll
    for (int i = 0; i < 4; i++)
        tile[ty + 8 * i][tx] =
            __half2float(src[(size_t)(s0 + ty + 8 * i) * HH + h0 + tx]);
    __syncthreads();
#pragma unroll
    for (int i = 0; i < 4; i++)
        dst[(size_t)(h0 + ty + 8 * i) * TT + s0 + tx] =
            __float2half_rn(tile[tx][ty + 8 * i]);  // exact round-trip
}

// S = (Q K^T) * E^-0.5 (fp32 out), causal; grid (TT/BN, TT/BM, BQ).
// Strictly-below-diagonal tiles (n0 < m0): every element passes the causal
// test -> fast float2 epilogue. Only diagonal tiles predicate per element.
__global__ void __launch_bounds__(256) score_kernel() {
    int b = blockIdx.z;
    int m0 = blockIdx.y * BM, n0 = blockIdx.x * BN;
    if (n0 > m0) return;  // tile entirely above the diagonal -> never read
    const __half* Q = g_q + (size_t)b * TT * HH;
    const __half* Kp = g_k + (size_t)b * TT * HH;
    float* S = g_s + (size_t)b * TT * TT;
    if (n0 == m0)
        gemm_nt<true >(Q, Kp, S, HH, HH, TT, HH, m0, n0, 0.03125f);  // 1024^-0.5
    else
        gemm_nt<false>(Q, Kp, S, HH, HH, TT, HH, m0, n0, 0.03125f);
}

// Row-wise causal softmax: reads fp32 S (float4), writes fp16 P (uint4).
// Thread t owns contiguous cols [8t, 8t+8). Zero-fills up to the 128-rounded
// boundary pv reads (limit divisible by 8 -> whole vector groups).
// Upper-triangle over-reads hit zero-initialized g_s: deterministic, masked.
// grid (BQ*TT)
__global__ void __launch_bounds__(256) softmax_kernel() {
    const int row = blockIdx.x;
    const int b = row >> 11;
    const int t = row & (TT - 1);
    const float* S = g_s + (size_t)b * TT * TT + (size_t)t * TT;
    __half* P = g_p + (size_t)b * TT * TT + (size_t)t * TT;
    const int tid = threadIdx.x;
    const int lane = tid & 31, warp = tid >> 5;
    const int limit = (t & ~127) + 128;  // pv reads cols [0, limit)
    const int j0 = tid * 8;
    __shared__ float red[8];

    float v[8];
    const float4 s0 = reinterpret_cast<const float4*>(S + j0)[0];
    const float4 s1 = reinterpret_cast<const float4*>(S + j0)[1];
    v[0] = s0.x; v[1] = s0.y; v[2] = s0.z; v[3] = s0.w;
    v[4] = s1.x; v[5] = s1.y; v[6] = s1.z; v[7] = s1.w;

    float mx = -INFINITY;
#pragma unroll
    for (int i = 0; i < 8; i++) {
        if (j0 + i > t) v[i] = -INFINITY;
        mx = fmaxf(mx, v[i]);
    }
#pragma unroll
    for (int o = 16; o; o >>= 1) mx = fmaxf(mx, __shfl_xor_sync(0xffffffffu, mx, o));
    if (lane == 0) red[warp] = mx;
    __syncthreads();
    float bm = red[0];
#pragma unroll
    for (int w = 1; w < 8; w++) bm = fmaxf(bm, red[w]);
    __syncthreads();

    float sum = 0.f;
#pragma unroll
    for (int i = 0; i < 8; i++) {
        float e = (j0 + i <= t) ? __expf(v[i] - bm) : 0.f;
        v[i] = e;
        sum += e;
    }
#pragma unroll
    for (int o = 16; o; o >>= 1) sum += __shfl_xor_sync(0xffffffffu, sum, o);
    if (lane == 0) red[warp] = sum;
    __syncthreads();
    float tot = 0.f;
#pragma unroll
    for (int w = 0; w < 8; w++) tot += red[w];
    float inv = 1.f / tot;

    if (j0 < limit) {
        __half2 h[4];
#pragma unroll
        for (int i = 0; i < 4; i++)
            h[i] = __floats2half2_rn(v[2 * i] * inv, v[2 * i + 1] * inv);
        *reinterpret_cast<uint4*>(P + j0) = *reinterpret_cast<uint4*>(h);
    }
}

// O = P Vt^T ; grid (HH/BN, TT/BM, BQ). K truncated at m0+128 (P zero
// beyond). Heavy tiles (large m0 -> large K) launch FIRST for wave packing.
__global__ void __launch_bounds__(256) pv_kernel(float* __restrict__ out) {
    int b = blockIdx.z;
    int m0 = (gridDim.y - 1 - blockIdx.y) * BM;   // reversed: heavy first
    int n0 = blockIdx.x * BN;
    const __half* P = g_p + (size_t)b * TT * TT;
    const __half* Vt = g_vt + (size_t)b * HH * TT;
    float* C = out + (size_t)b * TT * HH;
    gemm_nt<false>(P, Vt, C, TT, TT, HH, m0 + BM, m0, n0, 1.0f);
}

// ---------------------------------------------------------------------------
extern "C" void kernel_launch(void* const* d_in, const int* in_sizes, int n_in,
                              void* d_out, int out_size) {
    const float* x  = (const float*)d_in[0];
    const float* Wk = (const float*)d_in[1];
    const float* Wq = (const float*)d_in[2];
    const float* Wv = (const float*)d_in[3];
    float* out = (float*)d_out;

    static int smem_set = 0;
    if (!smem_set) {
        cudaFuncSetAttribute(qkv_kernel,   cudaFuncAttributeMaxDynamicSharedMemorySize, SMEM_GEMM);
        cudaFuncSetAttribute(score_kernel, cudaFuncAttributeMaxDynamicSharedMemorySize, SMEM_GEMM);
        cudaFuncSetAttribute(pv_kernel,    cudaFuncAttributeMaxDynamicSharedMemorySize, SMEM_GEMM);
        smem_set = 1;
    }

    dim3 blk(256);
    const int X4 = (BQ * TT * EE) / 4;
    const int W4 = (HH * EE) / 4;

    tohalf_kernel<<<X4 / 256, blk>>>((const float4*)x,  0);
    tohalf_kernel<<<W4 / 256, blk>>>((const float4*)Wq, 1);
    tohalf_kernel<<<W4 / 256, blk>>>((const float4*)Wk, 2);
    tohalf_kernel<<<W4 / 256, blk>>>((const float4*)Wv, 3);

    qkv_kernel<<<dim3(HH / BN, (BQ * TT) / BM, 3), blk, SMEM_GEMM>>>();
    transpose_kernel<<<dim3(HH / 32, TT / 32, BQ), dim3(32, 8)>>>();
    score_kernel<<<dim3(TT / BN, TT / BM, BQ), blk, SMEM_GEMM>>>();
    softmax_kernel<<<dim3(BQ * TT), blk>>>();
    pv_kernel<<<dim3(HH / BN, TT / BM, BQ), blk, SMEM_GEMM>>>(out);
}

// round 17
// speedup vs baseline: 2.0612x; 1.1462x over previous
#include <cuda_runtime.h>
#include <cuda_fp16.h>
#include <math.h>
#include <type_traits>

// Problem dims
#define BQ 8
#define TT 2048
#define EE 1024
#define HH 1024

// GEMM tile config: CTA 128x128, 8 warps (4m x 2n), warp tile 32x64,
// fp16 m16n8k16 mma, K staged in 64-wide chunks, 3-stage cp.async ring.
#define BM 128
#define BN 128
#define BKT 64
#define LDASH 72                        // 64 + 8 pad (halves); conflict-free
#define STG_HALVES (BM * LDASH)         // 9216 halves = 18432 B per operand stage
#define STAGES 3
#define SMEM_GEMM (STAGES * 2 * STG_HALVES * 2)  // 110592 B -> 2 CTAs/SM
#define LDT 136                         // transpose tile row stride (halves):
                                        // r*68 mod 32 spans all banks

// Scratch (allocation-free rule: __device__ globals; device-side access ONLY —
// taking these symbols' addresses from host code was the R7 silent-zero bug)
__device__ __half g_x [(long long)BQ * TT * EE];   // fp16 x
__device__ __half g_wq[(long long)HH * EE];        // fp16 weights
__device__ __half g_wk[(long long)HH * EE];
__device__ __half g_wv[(long long)HH * EE];
__device__ __half g_q [(long long)BQ * TT * HH];   // fp16 Q/K
__device__ __half g_k [(long long)BQ * TT * HH];
__device__ __half g_vt[(long long)BQ * HH * TT];   // V transposed [b][h][s]
__device__ float  g_s [(long long)BQ * TT * TT];   // raw scores (fp32 for softmax)
__device__ __half g_p [(long long)BQ * TT * TT];   // probabilities (fp16)

__device__ __forceinline__ void mma_f16(float* c,
                                        unsigned a0, unsigned a1, unsigned a2, unsigned a3,
                                        unsigned b0, unsigned b1) {
    asm volatile(
        "mma.sync.aligned.m16n8k16.row.col.f32.f16.f16.f32 "
        "{%0,%1,%2,%3}, {%4,%5,%6,%7}, {%8,%9}, {%0,%1,%2,%3};"
        : "+f"(c[0]), "+f"(c[1]), "+f"(c[2]), "+f"(c[3])
        : "r"(a0), "r"(a1), "r"(a2), "r"(a3), "r"(b0), "r"(b1));
}

__device__ __forceinline__ void ldsm4(unsigned& r0, unsigned& r1,
                                      unsigned& r2, unsigned& r3, unsigned addr) {
    asm volatile("ldmatrix.sync.aligned.m8n8.x4.shared.b16 {%0,%1,%2,%3}, [%4];"
                 : "=r"(r0), "=r"(r1), "=r"(r2), "=r"(r3) : "r"(addr));
}

__device__ __forceinline__ unsigned smem_u32(const void* p) {
    return (unsigned)__cvta_generic_to_shared(p);
}
__device__ __forceinline__ void cp_async16(unsigned dst, const void* src) {
    asm volatile("cp.async.cg.shared.global [%0], [%1], 16;" :: "r"(dst), "l"(src));
}
__device__ __forceinline__ void cp_commit() { asm volatile("cp.async.commit_group;"); }
__device__ __forceinline__ void cp_wait1()  { asm volatile("cp.async.wait_group 1;"); }
__device__ __forceinline__ void cp_wait0()  { asm volatile("cp.async.wait_group 0;"); }

// ---------------------------------------------------------------------------
// C[M,N] = scale * A[M,K] * B[N,K]^T   (A,B fp16 row-major, K contiguous).
// 256 threads, 8 warps (4m x 2n), warp tile 32x64, m16n8k16 fp16 mma with
// fp32 accumulators. Fragments via ldmatrix.x4. 3-stage cp.async ring, ONE
// barrier per BKT=64 chunk; wait_group 0 on the final chunk.
// Epilogues:
//   TRANSV: smem-transposed fp16 store to C[(n0+c)*ldc + m_out + r]
//           (pipeline smem reused as a 128x(LDT) tile after the mainloop).
//   CAUSAL (OutT=float): per-element col<=row predicated stores.
//   OutT=__half: half2 stores; OutT=float non-causal: float2 stores.
// ---------------------------------------------------------------------------
template <bool CAUSAL, bool TRANSV, typename OutT>
__device__ __forceinline__ void gemm_nt(const __half* __restrict__ A,
                                        const __half* __restrict__ B,
                                        OutT* __restrict__ C,
                                        int lda, int ldb, int ldc,
                                        int K, int m0, int n0, int m_out,
                                        float scale) {
    extern __shared__ __half smh[];

    const int tid = threadIdx.x;
    const int warp = tid >> 5, lane = tid & 31;
    const int wm = warp >> 1;  // 0..3
    const int wn = warp & 1;   // 0..1

    float acc[2][8][4];
#pragma unroll
    for (int i = 0; i < 2; i++)
#pragma unroll
        for (int j = 0; j < 8; j++)
#pragma unroll
            for (int r = 0; r < 4; r++) acc[i][j][r] = 0.f;

    // ldmatrix lane addressing (lane = 8p+q supplies row-q address of matrix p).
    const int p = lane >> 3, q = lane & 7;
    int aoff[2], boff[4];
#pragma unroll
    for (int i = 0; i < 2; i++)
        aoff[i] = (wm * 32 + i * 16 + (p & 1) * 8 + q) * LDASH + (p >> 1) * 8;
#pragma unroll
    for (int jj = 0; jj < 4; jj++)
        boff[jj] = (wn * 64 + jj * 16 + (p >> 1) * 8 + q) * LDASH + (p & 1) * 8;

    // Staging: per stage each operand is 128 rows x 64 halves (128B) =
    // 1024 16B-chunks; 256 threads x 4. row = chunk>>3, halves = (chunk&7)*8.
    auto issue = [&](int s, int ktw) {
        __half* as = smh + s * 2 * STG_HALVES;
        __half* bs = as + STG_HALVES;
#pragma unroll
        for (int pc = 0; pc < 4; pc++) {
            int chunk = tid + 256 * pc;
            int row = chunk >> 3;
            int cw = (chunk & 7) * 8;
            cp_async16(smem_u32(&as[row * LDASH + cw]),
                       A + (size_t)(m0 + row) * lda + ktw + cw);
            cp_async16(smem_u32(&bs[row * LDASH + cw]),
                       B + (size_t)(n0 + row) * ldb + ktw + cw);
        }
        cp_commit();
    };

    const int nk = K / BKT;   // >= 2 for all call sites
    issue(0, 0);
    if (nk > 1) issue(1, BKT);

    for (int kt = 0; kt < nk; kt++) {
        if (kt == nk - 1) cp_wait0(); else cp_wait1();
        __syncthreads();
        // Stage (kt+2)%3 was last read in iteration kt-1, finished by every
        // warp before this barrier; issue strictly after it.
        if (kt + 2 < nk) issue((kt + 2) % STAGES, (kt + 2) * BKT);

        const __half* as = smh + (kt % STAGES) * 2 * STG_HALVES;
        const __half* bs = as + STG_HALVES;
        const unsigned abase = smem_u32(as);
        const unsigned bbase = smem_u32(bs);

#pragma unroll
        for (int ks = 0; ks < BKT; ks += 16) {
            unsigned a[2][4], b[8][2];
            ldsm4(a[0][0], a[0][1], a[0][2], a[0][3], abase + (aoff[0] + ks) * 2);
            ldsm4(a[1][0], a[1][1], a[1][2], a[1][3], abase + (aoff[1] + ks) * 2);
            ldsm4(b[0][0], b[0][1], b[1][0], b[1][1], bbase + (boff[0] + ks) * 2);
            ldsm4(b[2][0], b[2][1], b[3][0], b[3][1], bbase + (boff[1] + ks) * 2);
            ldsm4(b[4][0], b[4][1], b[5][0], b[5][1], bbase + (boff[2] + ks) * 2);
            ldsm4(b[6][0], b[6][1], b[7][0], b[7][1], bbase + (boff[3] + ks) * 2);
#pragma unroll
            for (int i = 0; i < 2; i++)
#pragma unroll
                for (int j = 0; j < 8; j++)
                    mma_f16(acc[i][j], a[i][0], a[i][1], a[i][2], a[i][3],
                            b[j][0], b[j][1]);
        }
    }

    if constexpr (TRANSV) {
        // All warps done reading pipeline smem before we repurpose it.
        __syncthreads();
        __half* tile = smh;  // 128 x LDT fp16 tile (34816 B < SMEM_GEMM)
        // Phase 1: half2 stores at [local r][local c] (same pattern as the
        // proven gmem epilogue; LDT=136 keeps it conflict-free).
#pragma unroll
        for (int i = 0; i < 2; i++) {
            int rl0 = wm * 32 + i * 16 + (lane >> 2);
#pragma unroll
            for (int j = 0; j < 8; j++) {
                int cl = wn * 64 + j * 8 + (lane & 3) * 2;
#pragma unroll
                for (int h = 0; h < 2; h++) {
                    int rl = rl0 + h * 8;
                    *reinterpret_cast<__half2*>(&tile[rl * LDT + cl]) =
                        __floats2half2_rn(acc[i][j][2 * h + 0] * scale,
                                          acc[i][j][2 * h + 1] * scale);
                }
            }
        }
        __syncthreads();
        // Phase 2: column reads (16 distinct words/warp -> conflict-free),
        // 16B-vectorized stores of Vt rows. Thread t: col c = t&127,
        // row-half (t>>7)*64.
        const int c = tid & 127;
        const int rh = (tid >> 7) * 64;
        OutT* dst = C + (size_t)(n0 + c) * ldc + m_out + rh;
#pragma unroll
        for (int blk = 0; blk < 64; blk += 8) {
            __half hbuf[8];
#pragma unroll
            for (int k = 0; k < 8; k++)
                hbuf[k] = tile[(rh + blk + k) * LDT + c];
            *reinterpret_cast<uint4*>(dst + blk) = *reinterpret_cast<uint4*>(hbuf);
        }
        return;
    }

#pragma unroll
    for (int i = 0; i < 2; i++) {
        int rbase = m_out + wm * 32 + i * 16 + (lane >> 2);
#pragma unroll
        for (int j = 0; j < 8; j++) {
            int cn = n0 + wn * 64 + j * 8 + (lane & 3) * 2;
#pragma unroll
            for (int h = 0; h < 2; h++) {
                int r = rbase + h * 8;
                float v0 = acc[i][j][2 * h + 0] * scale;
                float v1 = acc[i][j][2 * h + 1] * scale;
                if constexpr (std::is_same<OutT, __half>::value) {
                    *reinterpret_cast<__half2*>(C + (size_t)r * ldc + cn) =
                        __floats2half2_rn(v0, v1);
                } else if constexpr (CAUSAL) {
                    if (cn <= r)     C[(size_t)r * ldc + cn]     = v0;
                    if (cn + 1 <= r) C[(size_t)r * ldc + cn + 1] = v1;
                } else {
                    *reinterpret_cast<float2*>(C + (size_t)r * ldc + cn) =
                        make_float2(v0, v1);
                }
            }
        }
    }
}

// ---------------------------------------------------------------------------
// Kernels
// ---------------------------------------------------------------------------

// fp32 -> fp16 pre-convert of x; dst selected DEVICE-SIDE.
__global__ void __launch_bounds__(256) tohalf_x_kernel(const float4* __restrict__ src) {
    __half2* dst = reinterpret_cast<__half2*>(g_x);
    int i = blockIdx.x * 256 + threadIdx.x;
    float4 v = src[i];
    dst[2 * i]     = __floats2half2_rn(v.x, v.y);
    dst[2 * i + 1] = __floats2half2_rn(v.z, v.w);
}

// fp32 -> fp16 pre-convert of the 3 weights in ONE launch; grid.z selects.
__global__ void __launch_bounds__(256) tohalf_w_kernel(const float4* __restrict__ wq,
                                                       const float4* __restrict__ wk,
                                                       const float4* __restrict__ wv) {
    const float4* src;
    __half2* dst;
    switch (blockIdx.z) {
        case 0:  src = wq; dst = reinterpret_cast<__half2*>(g_wq); break;
        case 1:  src = wk; dst = reinterpret_cast<__half2*>(g_wk); break;
        default: src = wv; dst = reinterpret_cast<__half2*>(g_wv); break;
    }
    int i = blockIdx.x * 256 + threadIdx.x;
    float4 v = src[i];
    dst[2 * i]     = __floats2half2_rn(v.x, v.y);
    dst[2 * i + 1] = __floats2half2_rn(v.z, v.w);
}

// Q/K = x @ W^T -> g_q/g_k; V = x @ Wv^T -> g_vt DIRECTLY (transposing
// epilogue; no g_v, no separate transpose kernel).
// grid (HH/BN, (BQ*TT)/BM, 3)
__global__ void __launch_bounds__(256) qkv_kernel() {
    int m0 = blockIdx.y * BM, n0 = blockIdx.x * BN;
    switch (blockIdx.z) {
        case 0:
            gemm_nt<false, false>(g_x, g_wq, g_q, EE, EE, HH, EE, m0, n0, m0, 1.0f);
            break;
        case 1:
            gemm_nt<false, false>(g_x, g_wk, g_k, EE, EE, HH, EE, m0, n0, m0, 1.0f);
            break;
        default: {
            int b = m0 >> 11;            // m0 / TT
            int s0 = m0 & (TT - 1);      // tiles never straddle batches (TT%BM==0)
            gemm_nt<false, true>(g_x, g_wv, g_vt + (size_t)b * HH * TT,
                                 EE, EE, TT, EE, m0, n0, s0, 1.0f);
            break;
        }
    }
}

// S = (Q K^T) * E^-0.5 (fp32 out), causal; grid (TT/BN, TT/BM, BQ).
// Strictly-below-diagonal tiles: fast float2 epilogue; diagonal: predicated.
__global__ void __launch_bounds__(256) score_kernel() {
    int b = blockIdx.z;
    int m0 = blockIdx.y * BM, n0 = blockIdx.x * BN;
    if (n0 > m0) return;  // tile entirely above the diagonal -> never read
    const __half* Q = g_q + (size_t)b * TT * HH;
    const __half* Kp = g_k + (size_t)b * TT * HH;
    float* S = g_s + (size_t)b * TT * TT;
    if (n0 == m0)
        gemm_nt<true,  false>(Q, Kp, S, HH, HH, TT, HH, m0, n0, m0, 0.03125f);
    else
        gemm_nt<false, false>(Q, Kp, S, HH, HH, TT, HH, m0, n0, m0, 0.03125f);
}

// Row-wise causal softmax: reads fp32 S (float4, ONLY cols < limit),
// writes fp16 P (uint4). Thread t owns contiguous cols [8t, 8t+8).
// limit = 128-rounded boundary pv reads; divisible by 8 -> whole vectors.
// grid (BQ*TT)
__global__ void __launch_bounds__(256) softmax_kernel() {
    const int row = blockIdx.x;
    const int b = row >> 11;
    const int t = row & (TT - 1);
    const float* S = g_s + (size_t)b * TT * TT + (size_t)t * TT;
    __half* P = g_p + (size_t)b * TT * TT + (size_t)t * TT;
    const int tid = threadIdx.x;
    const int lane = tid & 31, warp = tid >> 5;
    const int limit = (t & ~127) + 128;  // pv reads cols [0, limit)
    const int j0 = tid * 8;
    const bool active = (j0 < limit);
    __shared__ float red[8];

    float v[8];
    if (active) {
        const float4 s0 = reinterpret_cast<const float4*>(S + j0)[0];
        const float4 s1 = reinterpret_cast<const float4*>(S + j0)[1];
        v[0] = s0.x; v[1] = s0.y; v[2] = s0.z; v[3] = s0.w;
        v[4] = s1.x; v[5] = s1.y; v[6] = s1.z; v[7] = s1.w;
    } else {
#pragma unroll
        for (int i = 0; i < 8; i++) v[i] = -INFINITY;
    }

    float mx = -INFINITY;
#pragma unroll
    for (int i = 0; i < 8; i++) {
        if (j0 + i > t) v[i] = -INFINITY;
        mx = fmaxf(mx, v[i]);
    }
#pragma unroll
    for (int o = 16; o; o >>= 1) mx = fmaxf(mx, __shfl_xor_sync(0xffffffffu, mx, o));
    if (lane == 0) red[warp] = mx;
    __syncthreads();
    float bm = red[0];
#pragma unroll
    for (int w = 1; w < 8; w++) bm = fmaxf(bm, red[w]);
    __syncthreads();

    float sum = 0.f;
#pragma unroll
    for (int i = 0; i < 8; i++) {
        float e = (j0 + i <= t) ? __expf(v[i] - bm) : 0.f;
        v[i] = e;
        sum += e;
    }
#pragma unroll
    for (int o = 16; o; o >>= 1) sum += __shfl_xor_sync(0xffffffffu, sum, o);
    if (lane == 0) red[warp] = sum;
    __syncthreads();
    float tot = 0.f;
#pragma unroll
    for (int w = 0; w < 8; w++) tot += red[w];
    float inv = 1.f / tot;

    if (active) {
        __half2 h[4];
#pragma unroll
        for (int i = 0; i < 4; i++)
            h[i] = __floats2half2_rn(v[2 * i] * inv, v[2 * i + 1] * inv);
        *reinterpret_cast<uint4*>(P + j0) = *reinterpret_cast<uint4*>(h);
    }
}

// O = P Vt^T ; grid (HH/BN, TT/BM, BQ). K truncated at m0+128 (P zero
// beyond). Heavy tiles (large m0 -> large K) launch FIRST for wave packing.
__global__ void __launch_bounds__(256) pv_kernel(float* __restrict__ out) {
    int b = blockIdx.z;
    int m0 = (gridDim.y - 1 - blockIdx.y) * BM;   // reversed: heavy first
    int n0 = blockIdx.x * BN;
    const __half* P = g_p + (size_t)b * TT * TT;
    const __half* Vt = g_vt + (size_t)b * HH * TT;
    float* C = out + (size_t)b * TT * HH;
    gemm_nt<false, false>(P, Vt, C, TT, TT, HH, m0 + BM, m0, n0, m0, 1.0f);
}

// ---------------------------------------------------------------------------
extern "C" void kernel_launch(void* const* d_in, const int* in_sizes, int n_in,
                              void* d_out, int out_size) {
    const float* x  = (const float*)d_in[0];
    const float* Wk = (const float*)d_in[1];
    const float* Wq = (const float*)d_in[2];
    const float* Wv = (const float*)d_in[3];
    float* out = (float*)d_out;

    static int smem_set = 0;
    if (!smem_set) {
        cudaFuncSetAttribute(qkv_kernel,   cudaFuncAttributeMaxDynamicSharedMemorySize, SMEM_GEMM);
        cudaFuncSetAttribute(score_kernel, cudaFuncAttributeMaxDynamicSharedMemorySize, SMEM_GEMM);
        cudaFuncSetAttribute(pv_kernel,    cudaFuncAttributeMaxDynamicSharedMemorySize, SMEM_GEMM);
        smem_set = 1;
    }

    dim3 blk(256);
    const int X4 = (BQ * TT * EE) / 4;
    const int W4 = (HH * EE) / 4;

    tohalf_x_kernel<<<X4 / 256, blk>>>((const float4*)x);
    tohalf_w_kernel<<<dim3(W4 / 256, 1, 3), blk>>>(
        (const float4*)Wq, (const float4*)Wk, (const float4*)Wv);

    qkv_kernel<<<dim3(HH / BN, (BQ * TT) / BM, 3), blk, SMEM_GEMM>>>();
    score_kernel<<<dim3(TT / BN, TT / BM, BQ), blk, SMEM_GEMM>>>();
    softmax_kernel<<<dim3(BQ * TT), blk>>>();
    pv_kernel<<<dim3(HH / BN, TT / BM, BQ), blk, SMEM_GEMM>>>(out);
}